// round 1
// baseline (speedup 1.0000x reference)
#include <cuda_runtime.h>
#include <math.h>

#define Vv 32000
#define Hh 512
#define Bb 128
#define Ss 64

// ---- scratch (single __device__ global, no allocations) ----
// layout: Wh [B*H] | We [B*S*H] | rnn_in [B*2H] | gates [B*4H]
#define OFF_WH   0
#define OFF_WE   (Bb*Hh)                       // 65536
#define OFF_RNN  (OFF_WE + Bb*Ss*Hh)           // 4259840
#define OFF_GATE (OFF_RNN + Bb*2*Hh)           // 4390912
#define SCRATCH_TOTAL (OFF_GATE + Bb*4*Hh)     // 4653056 floats (~18.6 MB)
__device__ float g_scratch[SCRATCH_TOTAL];

__device__ __forceinline__ float sigmoidf_(float x) {
    return 1.0f / (1.0f + __expf(-x));
}

// ============================================================
// Generic tiled SGEMM:  C[M,N] (+)= A[M,K] @ B[N,K]^T (+ bias)
// Both A and B are K-major row-major (activation / weight layouts).
// BM=BN=64, BK=16, 256 threads, 4x4 per-thread microtile.
// All problem dims here are multiples of the tile sizes.
// ============================================================
template<bool ACC, bool BIAS>
__global__ __launch_bounds__(256)
void sgemm_tn(const float* __restrict__ A, int lda,
              const float* __restrict__ B, int ldb,
              float* __restrict__ C, int ldc,
              const float* __restrict__ bias,
              int M, int N, int K)
{
    __shared__ float As[16][68];   // padded: float4-aligned, reduced store conflicts
    __shared__ float Bs[16][68];

    const int m0 = blockIdx.y * 64;
    const int n0 = blockIdx.x * 64;
    const int t  = threadIdx.x;
    const int tx = t & 15;         // 0..15 -> n microtile
    const int ty = t >> 4;         // 0..15 -> m microtile
    const int lrow = t >> 2;       // 0..63 load row
    const int lk4  = (t & 3) * 4;  // 0,4,8,12 load k quad

    float acc[4][4];
    #pragma unroll
    for (int i = 0; i < 4; i++)
        #pragma unroll
        for (int j = 0; j < 4; j++) acc[i][j] = 0.0f;

    for (int kc = 0; kc < K; kc += 16) {
        float4 a = *(const float4*)&A[(size_t)(m0 + lrow) * lda + kc + lk4];
        float4 b = *(const float4*)&B[(size_t)(n0 + lrow) * ldb + kc + lk4];
        As[lk4+0][lrow] = a.x; As[lk4+1][lrow] = a.y;
        As[lk4+2][lrow] = a.z; As[lk4+3][lrow] = a.w;
        Bs[lk4+0][lrow] = b.x; Bs[lk4+1][lrow] = b.y;
        Bs[lk4+2][lrow] = b.z; Bs[lk4+3][lrow] = b.w;
        __syncthreads();

        #pragma unroll
        for (int kk = 0; kk < 16; kk++) {
            float4 av = *(const float4*)&As[kk][ty * 4];
            float4 bv = *(const float4*)&Bs[kk][tx * 4];
            float am[4] = {av.x, av.y, av.z, av.w};
            float bm[4] = {bv.x, bv.y, bv.z, bv.w};
            #pragma unroll
            for (int i = 0; i < 4; i++)
                #pragma unroll
                for (int j = 0; j < 4; j++)
                    acc[i][j] = fmaf(am[i], bm[j], acc[i][j]);
        }
        __syncthreads();
    }

    #pragma unroll
    for (int i = 0; i < 4; i++) {
        int m = m0 + ty * 4 + i;
        #pragma unroll
        for (int j = 0; j < 4; j++) {
            int n = n0 + tx * 4 + j;
            float vout = acc[i][j];
            if (BIAS) vout += bias[n];
            if (ACC)  vout += C[(size_t)m * ldc + n];
            C[(size_t)m * ldc + n] = vout;
        }
    }
}

// ============================================================
// Embedding gather -> rnn_in[:, 0:H]
// ============================================================
__global__ void embed_kernel(const int* __restrict__ input_ids,
                             const float* __restrict__ emb)
{
    int b = blockIdx.x;
    int h = threadIdx.x;          // 512 threads
    float* rnn_in = g_scratch + OFF_RNN;
    int idx = input_ids[b];
    rnn_in[(size_t)b * (2*Hh) + h] = emb[(size_t)idx * Hh + h];
}

// ============================================================
// scores = v . tanh(Wh[b] + We[b,s] + attn_b) ; softmax over s ;
// context -> rnn_in[:, H:2H].  One block per batch element.
// ============================================================
__global__ __launch_bounds__(256)
void attn_ctx_kernel(const float* __restrict__ enc,
                     const float* __restrict__ attn_b,
                     const float* __restrict__ v)
{
    const int b = blockIdx.x;
    const int t = threadIdx.x;
    const int lane = t & 31, warp = t >> 5;

    __shared__ float sWh[Hh], sab[Hh], sv[Hh];
    __shared__ float sscore[Ss], swgt[Ss];

    const float* Wh = g_scratch + OFF_WH + (size_t)b * Hh;
    const float* We = g_scratch + OFF_WE + (size_t)b * Ss * Hh;
    float* rnn_in   = g_scratch + OFF_RNN + (size_t)b * (2*Hh) + Hh;

    for (int h = t; h < Hh; h += 256) {
        sWh[h] = Wh[h];
        sab[h] = attn_b[h];
        sv[h]  = v[h];
    }
    __syncthreads();

    // scores: 8 warps x 8 s-positions each
    for (int s = warp; s < Ss; s += 8) {
        const float* we = We + (size_t)s * Hh;
        float sum = 0.0f;
        for (int h = lane; h < Hh; h += 32)
            sum += sv[h] * tanhf(sWh[h] + sab[h] + we[h]);
        #pragma unroll
        for (int off = 16; off > 0; off >>= 1)
            sum += __shfl_xor_sync(0xFFFFFFFFu, sum, off);
        if (lane == 0) sscore[s] = sum;
    }
    __syncthreads();

    // softmax over S=64 by warp 0 (2 values per lane)
    if (warp == 0) {
        float x0 = sscore[lane], x1 = sscore[lane + 32];
        float mx = fmaxf(x0, x1);
        #pragma unroll
        for (int off = 16; off > 0; off >>= 1)
            mx = fmaxf(mx, __shfl_xor_sync(0xFFFFFFFFu, mx, off));
        float e0 = expf(x0 - mx), e1 = expf(x1 - mx);
        float sum = e0 + e1;
        #pragma unroll
        for (int off = 16; off > 0; off >>= 1)
            sum += __shfl_xor_sync(0xFFFFFFFFu, sum, off);
        float inv = 1.0f / sum;
        swgt[lane]      = e0 * inv;
        swgt[lane + 32] = e1 * inv;
    }
    __syncthreads();

    // context[h] = sum_s w[s] * enc[b,s,h]
    const float* encb = enc + (size_t)b * Ss * Hh;
    for (int h = t; h < Hh; h += 256) {
        float a = 0.0f;
        #pragma unroll 8
        for (int s = 0; s < Ss; s++)
            a = fmaf(swgt[s], encb[(size_t)s * Hh + h], a);
        rnn_in[h] = a;
    }
}

// ============================================================
// LSTM pointwise: gates -> c_new, h_new (written into d_out tail)
// ============================================================
__global__ void lstm_kernel(const float* __restrict__ c0,
                            const float* __restrict__ b_ih,
                            const float* __restrict__ b_hh,
                            float* __restrict__ out)
{
    int b = blockIdx.x;
    int h = threadIdx.x;          // 512
    const float* g = g_scratch + OFF_GATE + (size_t)b * (4*Hh);

    float ig = g[h]          + b_ih[h]          + b_hh[h];
    float fg = g[Hh + h]     + b_ih[Hh + h]     + b_hh[Hh + h];
    float gg = g[2*Hh + h]   + b_ih[2*Hh + h]   + b_hh[2*Hh + h];
    float og = g[3*Hh + h]   + b_ih[3*Hh + h]   + b_hh[3*Hh + h];

    float cn = sigmoidf_(fg) * c0[(size_t)b * Hh + h]
             + sigmoidf_(ig) * tanhf(gg);
    float hn = sigmoidf_(og) * tanhf(cn);

    out[(size_t)Bb * Vv + (size_t)b * Hh + h] = hn;                    // h_new
    out[(size_t)Bb * Vv + (size_t)Bb * Hh + (size_t)b * Hh + h] = cn;  // c_new
}

// ============================================================
// kernel_launch
// ============================================================
extern "C" void kernel_launch(void* const* d_in, const int* in_sizes, int n_in,
                              void* d_out, int out_size)
{
    const int*   input_ids = (const int*)  d_in[0];
    const float* h0        = (const float*)d_in[1];   // [1,B,H] -> [B,H]
    const float* c0        = (const float*)d_in[2];
    const float* enc       = (const float*)d_in[3];   // [B,S,H]
    const float* emb       = (const float*)d_in[4];   // [V,H]
    const float* attn_W    = (const float*)d_in[5];   // [H,2H]
    const float* attn_b    = (const float*)d_in[6];   // [H]
    const float* v         = (const float*)d_in[7];   // [H]
    const float* W_ih      = (const float*)d_in[8];   // [4H,2H]
    const float* W_hh      = (const float*)d_in[9];   // [4H,H]
    const float* b_ih      = (const float*)d_in[10];  // [4H]
    const float* b_hh      = (const float*)d_in[11];  // [4H]
    const float* fc_W      = (const float*)d_in[12];  // [V,H]
    const float* fc_b      = (const float*)d_in[13];  // [V]
    float* out = (float*)d_out;

    float* scratch = nullptr;
    cudaGetSymbolAddress((void**)&scratch, g_scratch);
    float* Wh     = scratch + OFF_WH;
    float* We     = scratch + OFF_WE;
    float* rnn_in = scratch + OFF_RNN;
    float* gates  = scratch + OFF_GATE;

    // 1) embedded -> rnn_in[:, 0:H]
    embed_kernel<<<Bb, Hh>>>(input_ids, emb);

    // 2) Wh = h0 @ attn_W[:, :H]^T      (M=128, N=512, K=512)
    sgemm_tn<false,false><<<dim3(Hh/64, Bb/64), 256>>>(
        h0, Hh, attn_W, 2*Hh, Wh, Hh, nullptr, Bb, Hh, Hh);

    // 3) We = enc @ attn_W[:, H:]^T     (M=8192, N=512, K=512)
    sgemm_tn<false,false><<<dim3(Hh/64, (Bb*Ss)/64), 256>>>(
        enc, Hh, attn_W + Hh, 2*Hh, We, Hh, nullptr, Bb*Ss, Hh, Hh);

    // 4) scores -> softmax -> context -> rnn_in[:, H:2H]
    attn_ctx_kernel<<<Bb, 256>>>(enc, attn_b, v);

    // 5) gates = rnn_in @ W_ih^T        (M=128, N=2048, K=1024)
    sgemm_tn<false,false><<<dim3((4*Hh)/64, Bb/64), 256>>>(
        rnn_in, 2*Hh, W_ih, 2*Hh, gates, 4*Hh, nullptr, Bb, 4*Hh, 2*Hh);

    // 6) gates += h0 @ W_hh^T           (M=128, N=2048, K=512)
    sgemm_tn<true,false><<<dim3((4*Hh)/64, Bb/64), 256>>>(
        h0, Hh, W_hh, Hh, gates, 4*Hh, nullptr, Bb, 4*Hh, Hh);

    // 7) LSTM pointwise -> h_new, c_new into d_out tail
    lstm_kernel<<<Bb, Hh>>>(c0, b_ih, b_hh, out);

    // 8) prediction = h_new @ fc_W^T + fc_b   (M=128, N=32000, K=512)
    const float* h_new = out + (size_t)Bb * Vv;
    sgemm_tn<false,true><<<dim3(Vv/64, Bb/64), 256>>>(
        h_new, Hh, fc_W, Hh, out, Vv, fc_b, Bb, Vv, Hh);
}

// round 2
// speedup vs baseline: 1.6114x; 1.6114x over previous
#include <cuda_runtime.h>
#include <math.h>
#include <stdint.h>

#define Vv 32000
#define Hh 512
#define Bb 128
#define Ss 64

// ---- scratch (single __device__ global, no allocations) ----
// layout: Wh [B*H] | We [B*S*H] | rnn_in [B*2H] | gates [B*4H] | scores [B*S]
#define OFF_WH   0
#define OFF_WE   (Bb*Hh)
#define OFF_RNN  (OFF_WE + Bb*Ss*Hh)
#define OFF_GATE (OFF_RNN + Bb*2*Hh)
#define OFF_SC   (OFF_GATE + Bb*4*Hh)
#define SCRATCH_TOTAL (OFF_SC + Bb*Ss)
__device__ float g_scratch[SCRATCH_TOTAL];

__device__ __forceinline__ float sigmoidf_(float x) {
    return 1.0f / (1.0f + __expf(-x));
}

__device__ __forceinline__ uint32_t f2tf32(float x) {
    uint32_t r;
    asm("cvt.rna.tf32.f32 %0, %1;" : "=r"(r) : "f"(x));
    return r;
}

__device__ __forceinline__ void mma_tf32(float c[4],
    uint32_t a0, uint32_t a1, uint32_t a2, uint32_t a3,
    uint32_t b0, uint32_t b1)
{
    asm volatile(
        "mma.sync.aligned.m16n8k8.row.col.f32.tf32.tf32.f32 "
        "{%0,%1,%2,%3}, {%4,%5,%6,%7}, {%8,%9}, {%0,%1,%2,%3};"
        : "+f"(c[0]), "+f"(c[1]), "+f"(c[2]), "+f"(c[3])
        : "r"(a0), "r"(a1), "r"(a2), "r"(a3), "r"(b0), "r"(b1));
}

// ============================================================
// tf32 tensor-core GEMM:  C[M,N] (+)= A[M,K] @ B[N,K]^T (+ bias)
// BM=128, BN=64, BK=32. 256 threads = 8 warps in 4(m) x 2(n).
// Warp tile 32x32 = mma m16n8k8 fragments 2(m) x 4(n).
// M % 128 == 0, N % 64 == 0, K % 32 == 0 (true for all calls here).
// ============================================================
template<bool ACC, bool BIAS>
__global__ __launch_bounds__(256)
void mma_gemm(const float* __restrict__ A, int lda,
              const float* __restrict__ B, int ldb,
              float* __restrict__ C, int ldc,
              const float* __restrict__ bias,
              int M, int N, int K)
{
    __shared__ uint32_t As[128][36];   // stride 36: bank = (4*row + k) % 32 -> conflict-free frags
    __shared__ uint32_t Bs[64][36];

    const int m0 = blockIdx.y * 128;
    const int n0 = blockIdx.x * 64;
    const int t    = threadIdx.x;
    const int lane = t & 31;
    const int warp = t >> 5;
    const int wm = warp >> 1;      // 0..3
    const int wn = warp & 1;       // 0..1
    const int g  = lane >> 2;      // 0..7
    const int tg = lane & 3;       // 0..3

    float acc[2][4][4];
    #pragma unroll
    for (int mi = 0; mi < 2; mi++)
        #pragma unroll
        for (int ni = 0; ni < 4; ni++)
            #pragma unroll
            for (int k = 0; k < 4; k++) acc[mi][ni][k] = 0.0f;

    for (int kc = 0; kc < K; kc += 32) {
        // Load A tile 128x32 (4 float4/thread) and B tile 64x32 (2 float4/thread)
        #pragma unroll
        for (int i = 0; i < 4; i++) {
            int idx = t + 256 * i;
            int r   = idx >> 3;
            int c4  = (idx & 7) * 4;
            float4 v = *(const float4*)&A[(size_t)(m0 + r) * lda + kc + c4];
            uint4 u = make_uint4(f2tf32(v.x), f2tf32(v.y), f2tf32(v.z), f2tf32(v.w));
            *(uint4*)&As[r][c4] = u;
        }
        #pragma unroll
        for (int i = 0; i < 2; i++) {
            int idx = t + 256 * i;
            int r   = idx >> 3;
            int c4  = (idx & 7) * 4;
            float4 v = *(const float4*)&B[(size_t)(n0 + r) * ldb + kc + c4];
            uint4 u = make_uint4(f2tf32(v.x), f2tf32(v.y), f2tf32(v.z), f2tf32(v.w));
            *(uint4*)&Bs[r][c4] = u;
        }
        __syncthreads();

        #pragma unroll
        for (int kk = 0; kk < 32; kk += 8) {
            uint32_t af[2][4], bf[4][2];
            #pragma unroll
            for (int mi = 0; mi < 2; mi++) {
                int mr = wm * 32 + mi * 16;
                af[mi][0] = As[mr + g    ][kk + tg    ];
                af[mi][1] = As[mr + g + 8][kk + tg    ];
                af[mi][2] = As[mr + g    ][kk + tg + 4];
                af[mi][3] = As[mr + g + 8][kk + tg + 4];
            }
            #pragma unroll
            for (int ni = 0; ni < 4; ni++) {
                int nr = wn * 32 + ni * 8;
                bf[ni][0] = Bs[nr + g][kk + tg    ];
                bf[ni][1] = Bs[nr + g][kk + tg + 4];
            }
            #pragma unroll
            for (int mi = 0; mi < 2; mi++)
                #pragma unroll
                for (int ni = 0; ni < 4; ni++)
                    mma_tf32(acc[mi][ni],
                             af[mi][0], af[mi][1], af[mi][2], af[mi][3],
                             bf[ni][0], bf[ni][1]);
        }
        __syncthreads();
    }

    // Epilogue: c0/c1 = row g, cols 2tg/2tg+1 ; c2/c3 = row g+8
    #pragma unroll
    for (int mi = 0; mi < 2; mi++) {
        #pragma unroll
        for (int ci = 0; ci < 2; ci++) {
            int m = m0 + wm * 32 + mi * 16 + g + ci * 8;
            #pragma unroll
            for (int ni = 0; ni < 4; ni++) {
                int n = n0 + wn * 32 + ni * 8 + tg * 2;
                float2 vo;
                vo.x = acc[mi][ni][ci * 2 + 0];
                vo.y = acc[mi][ni][ci * 2 + 1];
                if (BIAS) { vo.x += bias[n]; vo.y += bias[n + 1]; }
                if (ACC) {
                    float2 old = *(const float2*)&C[(size_t)m * ldc + n];
                    vo.x += old.x; vo.y += old.y;
                }
                *(float2*)&C[(size_t)m * ldc + n] = vo;
            }
        }
    }
}

// ============================================================
// Embedding gather -> rnn_in[:, 0:H]
// ============================================================
__global__ void embed_kernel(const int* __restrict__ input_ids,
                             const float* __restrict__ emb)
{
    int b = blockIdx.x;
    int h = threadIdx.x;          // 512 threads
    float* rnn_in = g_scratch + OFF_RNN;
    int idx = input_ids[b];
    rnn_in[(size_t)b * (2*Hh) + h] = emb[(size_t)idx * Hh + h];
}

// ============================================================
// scores[b][s] = v . tanh(Wh[b] + We[b,s] + attn_b)
// grid (B, S/8), 256 threads; one warp per s position.
// ============================================================
__global__ __launch_bounds__(256)
void score_kernel(const float* __restrict__ attn_b,
                  const float* __restrict__ v)
{
    const int b = blockIdx.x;
    const int s = blockIdx.y * 8 + (threadIdx.x >> 5);
    const int lane = threadIdx.x & 31;

    const float* Wh = g_scratch + OFF_WH + (size_t)b * Hh;
    const float* We = g_scratch + OFF_WE + ((size_t)b * Ss + s) * Hh;

    float sum = 0.0f;
    #pragma unroll 4
    for (int h = lane; h < Hh; h += 32)
        sum += v[h] * tanhf(Wh[h] + attn_b[h] + We[h]);

    #pragma unroll
    for (int off = 16; off > 0; off >>= 1)
        sum += __shfl_xor_sync(0xFFFFFFFFu, sum, off);
    if (lane == 0)
        g_scratch[OFF_SC + (size_t)b * Ss + s] = sum;
}

// ============================================================
// softmax over s + context -> rnn_in[:, H:2H]
// grid (B, H/128), 128 threads; warp 0 redoes softmax (cheap).
// ============================================================
__global__ __launch_bounds__(128)
void ctx_kernel(const float* __restrict__ enc)
{
    const int b = blockIdx.x;
    const int t = threadIdx.x;
    __shared__ float swgt[Ss];

    if (t < 32) {
        float x0 = g_scratch[OFF_SC + (size_t)b * Ss + t];
        float x1 = g_scratch[OFF_SC + (size_t)b * Ss + t + 32];
        float mx = fmaxf(x0, x1);
        #pragma unroll
        for (int off = 16; off > 0; off >>= 1)
            mx = fmaxf(mx, __shfl_xor_sync(0xFFFFFFFFu, mx, off));
        float e0 = expf(x0 - mx), e1 = expf(x1 - mx);
        float sum = e0 + e1;
        #pragma unroll
        for (int off = 16; off > 0; off >>= 1)
            sum += __shfl_xor_sync(0xFFFFFFFFu, sum, off);
        float inv = 1.0f / sum;
        swgt[t]      = e0 * inv;
        swgt[t + 32] = e1 * inv;
    }
    __syncthreads();

    int h = blockIdx.y * 128 + t;
    const float* encb = enc + (size_t)b * Ss * Hh + h;
    float a = 0.0f;
    #pragma unroll 16
    for (int s = 0; s < Ss; s++)
        a = fmaf(swgt[s], encb[(size_t)s * Hh], a);
    g_scratch[OFF_RNN + (size_t)b * 2 * Hh + Hh + h] = a;
}

// ============================================================
// LSTM pointwise: gates -> c_new, h_new (written into d_out tail)
// ============================================================
__global__ void lstm_kernel(const float* __restrict__ c0,
                            const float* __restrict__ b_ih,
                            const float* __restrict__ b_hh,
                            float* __restrict__ out)
{
    int b = blockIdx.x;
    int h = threadIdx.x;          // 512
    const float* g = g_scratch + OFF_GATE + (size_t)b * (4*Hh);

    float ig = g[h]          + b_ih[h]          + b_hh[h];
    float fg = g[Hh + h]     + b_ih[Hh + h]     + b_hh[Hh + h];
    float gg = g[2*Hh + h]   + b_ih[2*Hh + h]   + b_hh[2*Hh + h];
    float og = g[3*Hh + h]   + b_ih[3*Hh + h]   + b_hh[3*Hh + h];

    float cn = sigmoidf_(fg) * c0[(size_t)b * Hh + h]
             + sigmoidf_(ig) * tanhf(gg);
    float hn = sigmoidf_(og) * tanhf(cn);

    out[(size_t)Bb * Vv + (size_t)b * Hh + h] = hn;                    // h_new
    out[(size_t)Bb * Vv + (size_t)Bb * Hh + (size_t)b * Hh + h] = cn;  // c_new
}

// ============================================================
// kernel_launch
// ============================================================
extern "C" void kernel_launch(void* const* d_in, const int* in_sizes, int n_in,
                              void* d_out, int out_size)
{
    const int*   input_ids = (const int*)  d_in[0];
    const float* h0        = (const float*)d_in[1];   // [1,B,H]
    const float* c0        = (const float*)d_in[2];
    const float* enc       = (const float*)d_in[3];   // [B,S,H]
    const float* emb       = (const float*)d_in[4];   // [V,H]
    const float* attn_W    = (const float*)d_in[5];   // [H,2H]
    const float* attn_b    = (const float*)d_in[6];   // [H]
    const float* v         = (const float*)d_in[7];   // [H]
    const float* W_ih      = (const float*)d_in[8];   // [4H,2H]
    const float* W_hh      = (const float*)d_in[9];   // [4H,H]
    const float* b_ih      = (const float*)d_in[10];  // [4H]
    const float* b_hh      = (const float*)d_in[11];  // [4H]
    const float* fc_W      = (const float*)d_in[12];  // [V,H]
    const float* fc_b      = (const float*)d_in[13];  // [V]
    float* out = (float*)d_out;

    float* scratch = nullptr;
    cudaGetSymbolAddress((void**)&scratch, g_scratch);
    float* Wh     = scratch + OFF_WH;
    float* We     = scratch + OFF_WE;
    float* rnn_in = scratch + OFF_RNN;
    float* gates  = scratch + OFF_GATE;

    // 1) embedded -> rnn_in[:, 0:H]
    embed_kernel<<<Bb, Hh>>>(input_ids, emb);

    // 2) Wh = h0 @ attn_W[:, :H]^T      (M=128, N=512, K=512)
    mma_gemm<false,false><<<dim3(Hh/64, Bb/128), 256>>>(
        h0, Hh, attn_W, 2*Hh, Wh, Hh, nullptr, Bb, Hh, Hh);

    // 3) We = enc @ attn_W[:, H:]^T     (M=8192, N=512, K=512)
    mma_gemm<false,false><<<dim3(Hh/64, (Bb*Ss)/128), 256>>>(
        enc, Hh, attn_W + Hh, 2*Hh, We, Hh, nullptr, Bb*Ss, Hh, Hh);

    // 4) scores (1024 CTAs), softmax+context (512 CTAs)
    score_kernel<<<dim3(Bb, Ss/8), 256>>>(attn_b, v);
    ctx_kernel<<<dim3(Bb, Hh/128), 128>>>(enc);

    // 5) gates = rnn_in @ W_ih^T        (M=128, N=2048, K=1024)
    mma_gemm<false,false><<<dim3((4*Hh)/64, Bb/128), 256>>>(
        rnn_in, 2*Hh, W_ih, 2*Hh, gates, 4*Hh, nullptr, Bb, 4*Hh, 2*Hh);

    // 6) gates += h0 @ W_hh^T           (M=128, N=2048, K=512)
    mma_gemm<true,false><<<dim3((4*Hh)/64, Bb/128), 256>>>(
        h0, Hh, W_hh, Hh, gates, 4*Hh, nullptr, Bb, 4*Hh, Hh);

    // 7) LSTM pointwise -> h_new, c_new into d_out tail
    lstm_kernel<<<Bb, Hh>>>(c0, b_ih, b_hh, out);

    // 8) prediction = h_new @ fc_W^T + fc_b   (M=128, N=32000, K=512)
    const float* h_new = out + (size_t)Bb * Vv;
    mma_gemm<false,true><<<dim3(Vv/64, Bb/128), 256>>>(
        h_new, Hh, fc_W, Hh, out, Vv, fc_b, Bb, Vv, Hh);
}

// round 3
// speedup vs baseline: 2.0632x; 1.2803x over previous
#include <cuda_runtime.h>
#include <math.h>
#include <stdint.h>

#define Vv 32000
#define Hh 512
#define Bb 128
#define Ss 64

// ---- scratch (single __device__ global, no allocations) ----
#define OFF_WH   0
#define OFF_WE   (Bb*Hh)
#define OFF_RNN  (OFF_WE + Bb*Ss*Hh)
#define OFF_GATE (OFF_RNN + Bb*2*Hh)
#define OFF_SC   (OFF_GATE + Bb*4*Hh)
#define SCRATCH_TOTAL (OFF_SC + Bb*Ss)
__device__ float g_scratch[SCRATCH_TOTAL];

__device__ __forceinline__ float sigmoidf_(float x) {
    return 1.0f / (1.0f + __expf(-x));
}
__device__ __forceinline__ float tanh_fast(float x) {
    float y;
    asm("tanh.approx.f32 %0, %1;" : "=f"(y) : "f"(x));
    return y;
}
__device__ __forceinline__ uint32_t f2tf32(float x) {
    uint32_t r;
    asm("cvt.rna.tf32.f32 %0, %1;" : "=r"(r) : "f"(x));
    return r;
}
__device__ __forceinline__ void mma_tf32(float c[4],
    uint32_t a0, uint32_t a1, uint32_t a2, uint32_t a3,
    uint32_t b0, uint32_t b1)
{
    asm volatile(
        "mma.sync.aligned.m16n8k8.row.col.f32.tf32.tf32.f32 "
        "{%0,%1,%2,%3}, {%4,%5,%6,%7}, {%8,%9}, {%0,%1,%2,%3};"
        : "+f"(c[0]), "+f"(c[1]), "+f"(c[2]), "+f"(c[3])
        : "r"(a0), "r"(a1), "r"(a2), "r"(a3), "r"(b0), "r"(b1));
}
__device__ __forceinline__ void cp_async16(void* sdst, const void* gsrc) {
    uint32_t d = (uint32_t)__cvta_generic_to_shared(sdst);
    asm volatile("cp.async.cg.shared.global [%0], [%1], 16;" :: "r"(d), "l"(gsrc));
}
__device__ __forceinline__ void cp_commit() {
    asm volatile("cp.async.commit_group;");
}

// ============================================================
// BIG tf32 GEMM: C[M,N] = A[M,K] @ B[N,K]^T (+bias)
// BM=128, BN=128, BK=16, double-buffered cp.async.
// 8 warps: wm=warp&1 (2 x 64 rows), wn=warp>>1 (4 x 32 cols).
// Warp tile 64x32 -> 4(mi) x 4(ni) m16n8k8 fragments.
// Requires M%128==0, N%128==0, K%16==0.
// ============================================================
template<bool BIAS>
__global__ __launch_bounds__(256)
void mma_gemm_big(const float* __restrict__ A, int lda,
                  const float* __restrict__ B, int ldb,
                  float* __restrict__ C, int ldc,
                  const float* __restrict__ bias,
                  int M, int N, int K)
{
    __shared__ float As[2][128][20];   // stride 20: (20g+tg)%32 distinct -> conflict-free
    __shared__ float Bs[2][128][20];

    const int m0 = blockIdx.y * 128;
    const int n0 = blockIdx.x * 128;
    const int t    = threadIdx.x;
    const int lane = t & 31;
    const int warp = t >> 5;
    const int wm = warp & 1;       // 0..1
    const int wn = warp >> 1;      // 0..3
    const int g  = lane >> 2;      // 0..7
    const int tg = lane & 3;       // 0..3

    // load mapping: idx = t + 256*i (i<2): row = idx>>2 (0..127), col4 = (idx&3)*4
    const int lr  = t >> 2;
    const int lc4 = (t & 3) * 4;

    float acc[4][4][4];
    #pragma unroll
    for (int mi = 0; mi < 4; mi++)
        #pragma unroll
        for (int ni = 0; ni < 4; ni++)
            #pragma unroll
            for (int k = 0; k < 4; k++) acc[mi][ni][k] = 0.0f;

    const int nk = K >> 4;

    // prefetch stage 0
    {
        cp_async16(&As[0][lr][lc4],      &A[(size_t)(m0 + lr) * lda + lc4]);
        cp_async16(&Bs[0][lr][lc4],      &B[(size_t)(n0 + lr) * ldb + lc4]);
        cp_async16(&As[0][lr + 64][lc4], &A[(size_t)(m0 + lr + 64) * lda + lc4]);
        cp_async16(&Bs[0][lr + 64][lc4], &B[(size_t)(n0 + lr + 64) * ldb + lc4]);
        cp_commit();
    }

    for (int kt = 0; kt < nk; kt++) {
        const int cur = kt & 1;
        if (kt + 1 < nk) {
            const int nxt = cur ^ 1;
            const int kc  = (kt + 1) << 4;
            cp_async16(&As[nxt][lr][lc4],      &A[(size_t)(m0 + lr) * lda + kc + lc4]);
            cp_async16(&Bs[nxt][lr][lc4],      &B[(size_t)(n0 + lr) * ldb + kc + lc4]);
            cp_async16(&As[nxt][lr + 64][lc4], &A[(size_t)(m0 + lr + 64) * lda + kc + lc4]);
            cp_async16(&Bs[nxt][lr + 64][lc4], &B[(size_t)(n0 + lr + 64) * ldb + kc + lc4]);
            cp_commit();
            asm volatile("cp.async.wait_group 1;");
        } else {
            asm volatile("cp.async.wait_group 0;");
        }
        __syncthreads();

        #pragma unroll
        for (int kk = 0; kk < 16; kk += 8) {
            uint32_t af[4][4], bf[4][2];
            #pragma unroll
            for (int mi = 0; mi < 4; mi++) {
                int mr = wm * 64 + mi * 16;
                af[mi][0] = f2tf32(As[cur][mr + g    ][kk + tg    ]);
                af[mi][1] = f2tf32(As[cur][mr + g + 8][kk + tg    ]);
                af[mi][2] = f2tf32(As[cur][mr + g    ][kk + tg + 4]);
                af[mi][3] = f2tf32(As[cur][mr + g + 8][kk + tg + 4]);
            }
            #pragma unroll
            for (int ni = 0; ni < 4; ni++) {
                int nr = wn * 32 + ni * 8;
                bf[ni][0] = f2tf32(Bs[cur][nr + g][kk + tg    ]);
                bf[ni][1] = f2tf32(Bs[cur][nr + g][kk + tg + 4]);
            }
            #pragma unroll
            for (int mi = 0; mi < 4; mi++)
                #pragma unroll
                for (int ni = 0; ni < 4; ni++)
                    mma_tf32(acc[mi][ni],
                             af[mi][0], af[mi][1], af[mi][2], af[mi][3],
                             bf[ni][0], bf[ni][1]);
        }
        __syncthreads();
    }

    #pragma unroll
    for (int mi = 0; mi < 4; mi++) {
        #pragma unroll
        for (int ci = 0; ci < 2; ci++) {
            int m = m0 + wm * 64 + mi * 16 + g + ci * 8;
            #pragma unroll
            for (int ni = 0; ni < 4; ni++) {
                int n = n0 + wn * 32 + ni * 8 + tg * 2;
                float2 vo;
                vo.x = acc[mi][ni][ci * 2 + 0];
                vo.y = acc[mi][ni][ci * 2 + 1];
                if (BIAS) { vo.x += bias[n]; vo.y += bias[n + 1]; }
                *(float2*)&C[(size_t)m * ldc + n] = vo;
            }
        }
    }
}

// ============================================================
// small tf32 GEMM (v1): BM=128, BN=64, BK=32 — for Wh/gates/Whh
// ============================================================
template<bool ACC, bool BIAS>
__global__ __launch_bounds__(256)
void mma_gemm(const float* __restrict__ A, int lda,
              const float* __restrict__ B, int ldb,
              float* __restrict__ C, int ldc,
              const float* __restrict__ bias,
              int M, int N, int K)
{
    __shared__ uint32_t As[128][36];
    __shared__ uint32_t Bs[64][36];

    const int m0 = blockIdx.y * 128;
    const int n0 = blockIdx.x * 64;
    const int t    = threadIdx.x;
    const int lane = t & 31;
    const int warp = t >> 5;
    const int wm = warp >> 1;
    const int wn = warp & 1;
    const int g  = lane >> 2;
    const int tg = lane & 3;

    float acc[2][4][4];
    #pragma unroll
    for (int mi = 0; mi < 2; mi++)
        #pragma unroll
        for (int ni = 0; ni < 4; ni++)
            #pragma unroll
            for (int k = 0; k < 4; k++) acc[mi][ni][k] = 0.0f;

    for (int kc = 0; kc < K; kc += 32) {
        #pragma unroll
        for (int i = 0; i < 4; i++) {
            int idx = t + 256 * i;
            int r   = idx >> 3;
            int c4  = (idx & 7) * 4;
            float4 v = *(const float4*)&A[(size_t)(m0 + r) * lda + kc + c4];
            uint4 u = make_uint4(f2tf32(v.x), f2tf32(v.y), f2tf32(v.z), f2tf32(v.w));
            *(uint4*)&As[r][c4] = u;
        }
        #pragma unroll
        for (int i = 0; i < 2; i++) {
            int idx = t + 256 * i;
            int r   = idx >> 3;
            int c4  = (idx & 7) * 4;
            float4 v = *(const float4*)&B[(size_t)(n0 + r) * ldb + kc + c4];
            uint4 u = make_uint4(f2tf32(v.x), f2tf32(v.y), f2tf32(v.z), f2tf32(v.w));
            *(uint4*)&Bs[r][c4] = u;
        }
        __syncthreads();

        #pragma unroll
        for (int kk = 0; kk < 32; kk += 8) {
            uint32_t af[2][4], bf[4][2];
            #pragma unroll
            for (int mi = 0; mi < 2; mi++) {
                int mr = wm * 32 + mi * 16;
                af[mi][0] = As[mr + g    ][kk + tg    ];
                af[mi][1] = As[mr + g + 8][kk + tg    ];
                af[mi][2] = As[mr + g    ][kk + tg + 4];
                af[mi][3] = As[mr + g + 8][kk + tg + 4];
            }
            #pragma unroll
            for (int ni = 0; ni < 4; ni++) {
                int nr = wn * 32 + ni * 8;
                bf[ni][0] = Bs[nr + g][kk + tg    ];
                bf[ni][1] = Bs[nr + g][kk + tg + 4];
            }
            #pragma unroll
            for (int mi = 0; mi < 2; mi++)
                #pragma unroll
                for (int ni = 0; ni < 4; ni++)
                    mma_tf32(acc[mi][ni],
                             af[mi][0], af[mi][1], af[mi][2], af[mi][3],
                             bf[ni][0], bf[ni][1]);
        }
        __syncthreads();
    }

    #pragma unroll
    for (int mi = 0; mi < 2; mi++) {
        #pragma unroll
        for (int ci = 0; ci < 2; ci++) {
            int m = m0 + wm * 32 + mi * 16 + g + ci * 8;
            #pragma unroll
            for (int ni = 0; ni < 4; ni++) {
                int n = n0 + wn * 32 + ni * 8 + tg * 2;
                float2 vo;
                vo.x = acc[mi][ni][ci * 2 + 0];
                vo.y = acc[mi][ni][ci * 2 + 1];
                if (BIAS) { vo.x += bias[n]; vo.y += bias[n + 1]; }
                if (ACC) {
                    float2 old = *(const float2*)&C[(size_t)m * ldc + n];
                    vo.x += old.x; vo.y += old.y;
                }
                *(float2*)&C[(size_t)m * ldc + n] = vo;
            }
        }
    }
}

// ============================================================
// Embedding gather -> rnn_in[:, 0:H]
// ============================================================
__global__ void embed_kernel(const int* __restrict__ input_ids,
                             const float* __restrict__ emb)
{
    int b = blockIdx.x;
    int h = threadIdx.x;
    float* rnn_in = g_scratch + OFF_RNN;
    int idx = input_ids[b];
    rnn_in[(size_t)b * (2*Hh) + h] = emb[(size_t)idx * Hh + h];
}

// ============================================================
// scores[b][s] = v . tanh(Wh[b] + We[b,s] + attn_b)
// ============================================================
__global__ __launch_bounds__(256)
void score_kernel(const float* __restrict__ attn_b,
                  const float* __restrict__ v)
{
    const int b = blockIdx.x;
    const int s = blockIdx.y * 8 + (threadIdx.x >> 5);
    const int lane = threadIdx.x & 31;

    const float* Wh = g_scratch + OFF_WH + (size_t)b * Hh;
    const float* We = g_scratch + OFF_WE + ((size_t)b * Ss + s) * Hh;

    float sum = 0.0f;
    #pragma unroll 4
    for (int h = lane; h < Hh; h += 32)
        sum += v[h] * tanh_fast(Wh[h] + attn_b[h] + We[h]);

    #pragma unroll
    for (int off = 16; off > 0; off >>= 1)
        sum += __shfl_xor_sync(0xFFFFFFFFu, sum, off);
    if (lane == 0)
        g_scratch[OFF_SC + (size_t)b * Ss + s] = sum;
}

// ============================================================
// softmax over s + context -> rnn_in[:, H:2H]
// ============================================================
__global__ __launch_bounds__(128)
void ctx_kernel(const float* __restrict__ enc)
{
    const int b = blockIdx.x;
    const int t = threadIdx.x;
    __shared__ float swgt[Ss];

    if (t < 32) {
        float x0 = g_scratch[OFF_SC + (size_t)b * Ss + t];
        float x1 = g_scratch[OFF_SC + (size_t)b * Ss + t + 32];
        float mx = fmaxf(x0, x1);
        #pragma unroll
        for (int off = 16; off > 0; off >>= 1)
            mx = fmaxf(mx, __shfl_xor_sync(0xFFFFFFFFu, mx, off));
        float e0 = expf(x0 - mx), e1 = expf(x1 - mx);
        float sum = e0 + e1;
        #pragma unroll
        for (int off = 16; off > 0; off >>= 1)
            sum += __shfl_xor_sync(0xFFFFFFFFu, sum, off);
        float inv = 1.0f / sum;
        swgt[t]      = e0 * inv;
        swgt[t + 32] = e1 * inv;
    }
    __syncthreads();

    int h = blockIdx.y * 128 + t;
    const float* encb = enc + (size_t)b * Ss * Hh + h;
    float a = 0.0f;
    #pragma unroll 16
    for (int s = 0; s < Ss; s++)
        a = fmaf(swgt[s], encb[(size_t)s * Hh], a);
    g_scratch[OFF_RNN + (size_t)b * 2 * Hh + Hh + h] = a;
}

// ============================================================
// LSTM pointwise
// ============================================================
__global__ void lstm_kernel(const float* __restrict__ c0,
                            const float* __restrict__ b_ih,
                            const float* __restrict__ b_hh,
                            float* __restrict__ out)
{
    int b = blockIdx.x;
    int h = threadIdx.x;
    const float* g = g_scratch + OFF_GATE + (size_t)b * (4*Hh);

    float ig = g[h]          + b_ih[h]          + b_hh[h];
    float fg = g[Hh + h]     + b_ih[Hh + h]     + b_hh[Hh + h];
    float gg = g[2*Hh + h]   + b_ih[2*Hh + h]   + b_hh[2*Hh + h];
    float og = g[3*Hh + h]   + b_ih[3*Hh + h]   + b_hh[3*Hh + h];

    float cn = sigmoidf_(fg) * c0[(size_t)b * Hh + h]
             + sigmoidf_(ig) * tanhf(gg);
    float hn = sigmoidf_(og) * tanhf(cn);

    out[(size_t)Bb * Vv + (size_t)b * Hh + h] = hn;
    out[(size_t)Bb * Vv + (size_t)Bb * Hh + (size_t)b * Hh + h] = cn;
}

// ============================================================
// kernel_launch
// ============================================================
extern "C" void kernel_launch(void* const* d_in, const int* in_sizes, int n_in,
                              void* d_out, int out_size)
{
    const int*   input_ids = (const int*)  d_in[0];
    const float* h0        = (const float*)d_in[1];
    const float* c0        = (const float*)d_in[2];
    const float* enc       = (const float*)d_in[3];
    const float* emb       = (const float*)d_in[4];
    const float* attn_W    = (const float*)d_in[5];
    const float* attn_b    = (const float*)d_in[6];
    const float* v         = (const float*)d_in[7];
    const float* W_ih      = (const float*)d_in[8];
    const float* W_hh      = (const float*)d_in[9];
    const float* b_ih      = (const float*)d_in[10];
    const float* b_hh      = (const float*)d_in[11];
    const float* fc_W      = (const float*)d_in[12];
    const float* fc_b      = (const float*)d_in[13];
    float* out = (float*)d_out;

    float* scratch = nullptr;
    cudaGetSymbolAddress((void**)&scratch, g_scratch);
    float* Wh     = scratch + OFF_WH;
    float* We     = scratch + OFF_WE;
    float* rnn_in = scratch + OFF_RNN;
    float* gates  = scratch + OFF_GATE;

    // 1) embedded -> rnn_in[:, 0:H]
    embed_kernel<<<Bb, Hh>>>(input_ids, emb);

    // 2) Wh = h0 @ attn_W[:, :H]^T      (M=128, N=512, K=512)
    mma_gemm<false,false><<<dim3(Hh/64, 1), 256>>>(
        h0, Hh, attn_W, 2*Hh, Wh, Hh, nullptr, Bb, Hh, Hh);

    // 3) We = enc @ attn_W[:, H:]^T     (M=8192, N=512, K=512)  [BIG]
    mma_gemm_big<false><<<dim3(Hh/128, (Bb*Ss)/128), 256>>>(
        enc, Hh, attn_W + Hh, 2*Hh, We, Hh, nullptr, Bb*Ss, Hh, Hh);

    // 4) scores, softmax+context
    score_kernel<<<dim3(Bb, Ss/8), 256>>>(attn_b, v);
    ctx_kernel<<<dim3(Bb, Hh/128), 128>>>(enc);

    // 5) gates = rnn_in @ W_ih^T        (M=128, N=2048, K=1024)
    mma_gemm<false,false><<<dim3((4*Hh)/64, 1), 256>>>(
        rnn_in, 2*Hh, W_ih, 2*Hh, gates, 4*Hh, nullptr, Bb, 4*Hh, 2*Hh);

    // 6) gates += h0 @ W_hh^T           (M=128, N=2048, K=512)
    mma_gemm<true,false><<<dim3((4*Hh)/64, 1), 256>>>(
        h0, Hh, W_hh, Hh, gates, 4*Hh, nullptr, Bb, 4*Hh, Hh);

    // 7) LSTM pointwise -> h_new, c_new
    lstm_kernel<<<Bb, Hh>>>(c0, b_ih, b_hh, out);

    // 8) prediction = h_new @ fc_W^T + fc_b   (M=128, N=32000, K=512) [BIG]
    const float* h_new = out + (size_t)Bb * Vv;
    mma_gemm_big<true><<<dim3(Vv/128, 1), 256>>>(
        h_new, Hh, fc_W, Hh, out, Vv, fc_b, Bb, Vv, Hh);
}

// round 4
// speedup vs baseline: 2.1529x; 1.0435x over previous
#include <cuda_runtime.h>
#include <math.h>
#include <stdint.h>

#define Vv 32000
#define Hh 512
#define Bb 128
#define Ss 64

// ---- scratch (single __device__ global, no allocations) ----
#define OFF_WH   0
#define OFF_WE   (Bb*Hh)
#define OFF_RNN  (OFF_WE + Bb*Ss*Hh)
#define OFF_GATE (OFF_RNN + Bb*2*Hh)
#define OFF_SC   (OFF_GATE + Bb*4*Hh)
#define SCRATCH_TOTAL (OFF_SC + Bb*Ss)
__device__ float g_scratch[SCRATCH_TOTAL];

__device__ __forceinline__ float sigmoidf_(float x) {
    return 1.0f / (1.0f + __expf(-x));
}
__device__ __forceinline__ float tanh_fast(float x) {
    float y;
    asm("tanh.approx.f32 %0, %1;" : "=f"(y) : "f"(x));
    return y;
}
__device__ __forceinline__ uint32_t f2tf32(float x) {
    uint32_t r;
    asm("cvt.rna.tf32.f32 %0, %1;" : "=r"(r) : "f"(x));
    return r;
}
__device__ __forceinline__ uint32_t f2tf32u(uint32_t xu) {
    return f2tf32(__uint_as_float(xu));
}
__device__ __forceinline__ void mma_tf32(float c[4],
    uint32_t a0, uint32_t a1, uint32_t a2, uint32_t a3,
    uint32_t b0, uint32_t b1)
{
    asm volatile(
        "mma.sync.aligned.m16n8k8.row.col.f32.tf32.tf32.f32 "
        "{%0,%1,%2,%3}, {%4,%5,%6,%7}, {%8,%9}, {%0,%1,%2,%3};"
        : "+f"(c[0]), "+f"(c[1]), "+f"(c[2]), "+f"(c[3])
        : "r"(a0), "r"(a1), "r"(a2), "r"(a3), "r"(b0), "r"(b1));
}
__device__ __forceinline__ void cp_async16(void* sdst, const void* gsrc) {
    uint32_t d = (uint32_t)__cvta_generic_to_shared(sdst);
    asm volatile("cp.async.cg.shared.global [%0], [%1], 16;" :: "r"(d), "l"(gsrc));
}
__device__ __forceinline__ void cp_commit() {
    asm volatile("cp.async.commit_group;");
}
__device__ __forceinline__ void ldsm_x4(uint32_t& r0, uint32_t& r1,
                                        uint32_t& r2, uint32_t& r3,
                                        uint32_t saddr)
{
    asm volatile("ldmatrix.sync.aligned.m8n8.x4.shared.b16 {%0,%1,%2,%3}, [%4];"
                 : "=r"(r0), "=r"(r1), "=r"(r2), "=r"(r3) : "r"(saddr));
}

// ============================================================
// tf32 GEMM: C[M,N] (+)= A[M,K] @ B[N,K]^T (+ bias)
// BM=128, BN=128, BK=16, double-buffered cp.async, ldmatrix frags.
// 8 warps: wm=warp&1 (2 x 64 rows), wn=warp>>1 (4 x 32 cols).
// Warp tile 64x32 -> 4(mi) x 4(ni) m16n8k8 fragments.
// Requires M%128==0, N%128==0, K%16==0.
// ============================================================
template<bool ACC, bool BIAS>
__global__ __launch_bounds__(256)
void mma_gemm_big(const float* __restrict__ A, int lda,
                  const float* __restrict__ B, int ldb,
                  float* __restrict__ C, int ldc,
                  const float* __restrict__ bias,
                  int M, int N, int K)
{
    __shared__ float As[2][128][20];   // stride 20: LDSM rows hit all 32 banks
    __shared__ float Bs[2][128][20];

    const int m0 = blockIdx.y * 128;
    const int n0 = blockIdx.x * 128;
    const int t    = threadIdx.x;
    const int lane = t & 31;
    const int warp = t >> 5;
    const int wm = warp & 1;       // 0..1
    const int wn = warp >> 1;      // 0..3
    const int g  = lane >> 2;      // 0..7
    const int tg = lane & 3;       // 0..3

    const int lr  = t >> 2;          // load row 0..63
    const int lc4 = (t & 3) * 4;     // load col quad

    // ldmatrix per-lane address offsets (bytes)
    const uint32_t as_base = (uint32_t)__cvta_generic_to_shared(&As[0][0][0]);
    const uint32_t bs_base = (uint32_t)__cvta_generic_to_shared(&Bs[0][0][0]);
    const uint32_t a_loff = (uint32_t)(((lane & 15) * 20 + ((lane >> 4) << 2)) * 4);
    const uint32_t b_loff = (uint32_t)((((lane & 7) + ((lane >> 4) << 3)) * 20
                                        + (((lane >> 3) & 1) << 2)) * 4);

    float acc[4][4][4];
    #pragma unroll
    for (int mi = 0; mi < 4; mi++)
        #pragma unroll
        for (int ni = 0; ni < 4; ni++)
            #pragma unroll
            for (int k = 0; k < 4; k++) acc[mi][ni][k] = 0.0f;

    const int nk = K >> 4;

    // prefetch stage 0
    {
        cp_async16(&As[0][lr][lc4],      &A[(size_t)(m0 + lr) * lda + lc4]);
        cp_async16(&Bs[0][lr][lc4],      &B[(size_t)(n0 + lr) * ldb + lc4]);
        cp_async16(&As[0][lr + 64][lc4], &A[(size_t)(m0 + lr + 64) * lda + lc4]);
        cp_async16(&Bs[0][lr + 64][lc4], &B[(size_t)(n0 + lr + 64) * ldb + lc4]);
        cp_commit();
    }

    for (int kt = 0; kt < nk; kt++) {
        const int cur = kt & 1;
        if (kt + 1 < nk) {
            const int nxt = cur ^ 1;
            const int kc  = (kt + 1) << 4;
            cp_async16(&As[nxt][lr][lc4],      &A[(size_t)(m0 + lr) * lda + kc + lc4]);
            cp_async16(&Bs[nxt][lr][lc4],      &B[(size_t)(n0 + lr) * ldb + kc + lc4]);
            cp_async16(&As[nxt][lr + 64][lc4], &A[(size_t)(m0 + lr + 64) * lda + kc + lc4]);
            cp_async16(&Bs[nxt][lr + 64][lc4], &B[(size_t)(n0 + lr + 64) * ldb + kc + lc4]);
            cp_commit();
            asm volatile("cp.async.wait_group 1;");
        } else {
            asm volatile("cp.async.wait_group 0;");
        }
        __syncthreads();

        const uint32_t abuf = as_base + (uint32_t)cur * 10240u;
        const uint32_t bbuf = bs_base + (uint32_t)cur * 10240u;

        #pragma unroll
        for (int kk = 0; kk < 16; kk += 8) {
            uint32_t af[4][4], bf[4][2];
            #pragma unroll
            for (int mi = 0; mi < 4; mi++) {
                uint32_t addr = abuf + (uint32_t)(((wm * 64 + mi * 16) * 20 + kk) * 4) + a_loff;
                ldsm_x4(af[mi][0], af[mi][1], af[mi][2], af[mi][3], addr);
            }
            {
                uint32_t addr0 = bbuf + (uint32_t)(((wn * 32) * 20 + kk) * 4) + b_loff;
                uint32_t addr1 = bbuf + (uint32_t)(((wn * 32 + 16) * 20 + kk) * 4) + b_loff;
                ldsm_x4(bf[0][0], bf[0][1], bf[1][0], bf[1][1], addr0);
                ldsm_x4(bf[2][0], bf[2][1], bf[3][0], bf[3][1], addr1);
            }
            #pragma unroll
            for (int mi = 0; mi < 4; mi++)
                #pragma unroll
                for (int j = 0; j < 4; j++)
                    af[mi][j] = f2tf32u(af[mi][j]);
            #pragma unroll
            for (int ni = 0; ni < 4; ni++) {
                bf[ni][0] = f2tf32u(bf[ni][0]);
                bf[ni][1] = f2tf32u(bf[ni][1]);
            }
            #pragma unroll
            for (int mi = 0; mi < 4; mi++)
                #pragma unroll
                for (int ni = 0; ni < 4; ni++)
                    mma_tf32(acc[mi][ni],
                             af[mi][0], af[mi][1], af[mi][2], af[mi][3],
                             bf[ni][0], bf[ni][1]);
        }
        __syncthreads();
    }

    #pragma unroll
    for (int mi = 0; mi < 4; mi++) {
        #pragma unroll
        for (int ci = 0; ci < 2; ci++) {
            int m = m0 + wm * 64 + mi * 16 + g + ci * 8;
            #pragma unroll
            for (int ni = 0; ni < 4; ni++) {
                int n = n0 + wn * 32 + ni * 8 + tg * 2;
                float2 vo;
                vo.x = acc[mi][ni][ci * 2 + 0];
                vo.y = acc[mi][ni][ci * 2 + 1];
                if (BIAS) { vo.x += bias[n]; vo.y += bias[n + 1]; }
                if (ACC) {
                    float2 old = *(const float2*)&C[(size_t)m * ldc + n];
                    vo.x += old.x; vo.y += old.y;
                }
                *(float2*)&C[(size_t)m * ldc + n] = vo;
            }
        }
    }
}

// ============================================================
// Embedding gather -> rnn_in[:, 0:H]
// ============================================================
__global__ void embed_kernel(const int* __restrict__ input_ids,
                             const float* __restrict__ emb)
{
    int b = blockIdx.x;
    int h = threadIdx.x;
    float* rnn_in = g_scratch + OFF_RNN;
    int idx = input_ids[b];
    rnn_in[(size_t)b * (2*Hh) + h] = emb[(size_t)idx * Hh + h];
}

// ============================================================
// scores[b][s] = v . tanh(Wh'[b] + We[b,s])   (Wh' has attn_b folded in)
// grid (B, S/8), 256 threads; one warp per (b,s). float4 loads.
// ============================================================
__global__ __launch_bounds__(256)
void score_kernel(const float* __restrict__ v)
{
    const int b = blockIdx.x;
    const int s = blockIdx.y * 8 + (threadIdx.x >> 5);
    const int lane = threadIdx.x & 31;

    const float4* Wh4 = (const float4*)(g_scratch + OFF_WH + (size_t)b * Hh);
    const float4* We4 = (const float4*)(g_scratch + OFF_WE + ((size_t)b * Ss + s) * Hh);
    const float4* v4  = (const float4*)v;

    float sum = 0.0f;
    #pragma unroll
    for (int i = lane; i < Hh/4; i += 32) {
        float4 w = Wh4[i];
        float4 e = We4[i];
        float4 vv = v4[i];
        sum += vv.x * tanh_fast(w.x + e.x);
        sum += vv.y * tanh_fast(w.y + e.y);
        sum += vv.z * tanh_fast(w.z + e.z);
        sum += vv.w * tanh_fast(w.w + e.w);
    }

    #pragma unroll
    for (int off = 16; off > 0; off >>= 1)
        sum += __shfl_xor_sync(0xFFFFFFFFu, sum, off);
    if (lane == 0)
        g_scratch[OFF_SC + (size_t)b * Ss + s] = sum;
}

// ============================================================
// softmax over s + context -> rnn_in[:, H:2H]
// ============================================================
__global__ __launch_bounds__(128)
void ctx_kernel(const float* __restrict__ enc)
{
    const int b = blockIdx.x;
    const int t = threadIdx.x;
    __shared__ float swgt[Ss];

    if (t < 32) {
        float x0 = g_scratch[OFF_SC + (size_t)b * Ss + t];
        float x1 = g_scratch[OFF_SC + (size_t)b * Ss + t + 32];
        float mx = fmaxf(x0, x1);
        #pragma unroll
        for (int off = 16; off > 0; off >>= 1)
            mx = fmaxf(mx, __shfl_xor_sync(0xFFFFFFFFu, mx, off));
        float e0 = expf(x0 - mx), e1 = expf(x1 - mx);
        float sum = e0 + e1;
        #pragma unroll
        for (int off = 16; off > 0; off >>= 1)
            sum += __shfl_xor_sync(0xFFFFFFFFu, sum, off);
        float inv = 1.0f / sum;
        swgt[t]      = e0 * inv;
        swgt[t + 32] = e1 * inv;
    }
    __syncthreads();

    int h = blockIdx.y * 128 + t;
    const float* encb = enc + (size_t)b * Ss * Hh + h;
    float a = 0.0f;
    #pragma unroll 16
    for (int s = 0; s < Ss; s++)
        a = fmaf(swgt[s], encb[(size_t)s * Hh], a);
    g_scratch[OFF_RNN + (size_t)b * 2 * Hh + Hh + h] = a;
}

// ============================================================
// LSTM pointwise
// ============================================================
__global__ void lstm_kernel(const float* __restrict__ c0,
                            const float* __restrict__ b_ih,
                            const float* __restrict__ b_hh,
                            float* __restrict__ out)
{
    int b = blockIdx.x;
    int h = threadIdx.x;
    const float* g = g_scratch + OFF_GATE + (size_t)b * (4*Hh);

    float ig = g[h]          + b_ih[h]          + b_hh[h];
    float fg = g[Hh + h]     + b_ih[Hh + h]     + b_hh[Hh + h];
    float gg = g[2*Hh + h]   + b_ih[2*Hh + h]   + b_hh[2*Hh + h];
    float og = g[3*Hh + h]   + b_ih[3*Hh + h]   + b_hh[3*Hh + h];

    float cn = sigmoidf_(fg) * c0[(size_t)b * Hh + h]
             + sigmoidf_(ig) * tanhf(gg);
    float hn = sigmoidf_(og) * tanhf(cn);

    out[(size_t)Bb * Vv + (size_t)b * Hh + h] = hn;
    out[(size_t)Bb * Vv + (size_t)Bb * Hh + (size_t)b * Hh + h] = cn;
}

// ============================================================
// kernel_launch
// ============================================================
extern "C" void kernel_launch(void* const* d_in, const int* in_sizes, int n_in,
                              void* d_out, int out_size)
{
    const int*   input_ids = (const int*)  d_in[0];
    const float* h0        = (const float*)d_in[1];
    const float* c0        = (const float*)d_in[2];
    const float* enc       = (const float*)d_in[3];
    const float* emb       = (const float*)d_in[4];
    const float* attn_W    = (const float*)d_in[5];
    const float* attn_b    = (const float*)d_in[6];
    const float* v         = (const float*)d_in[7];
    const float* W_ih      = (const float*)d_in[8];
    const float* W_hh      = (const float*)d_in[9];
    const float* b_ih      = (const float*)d_in[10];
    const float* b_hh      = (const float*)d_in[11];
    const float* fc_W      = (const float*)d_in[12];
    const float* fc_b      = (const float*)d_in[13];
    float* out = (float*)d_out;

    float* scratch = nullptr;
    cudaGetSymbolAddress((void**)&scratch, g_scratch);
    float* Wh     = scratch + OFF_WH;
    float* We     = scratch + OFF_WE;
    float* rnn_in = scratch + OFF_RNN;
    float* gates  = scratch + OFF_GATE;

    // 1) embedded -> rnn_in[:, 0:H]
    embed_kernel<<<Bb, Hh>>>(input_ids, emb);

    // 2) Wh = h0 @ attn_W[:, :H]^T + attn_b   (M=128, N=512, K=512)
    mma_gemm_big<false,true><<<dim3(Hh/128, 1), 256>>>(
        h0, Hh, attn_W, 2*Hh, Wh, Hh, attn_b, Bb, Hh, Hh);

    // 3) We = enc @ attn_W[:, H:]^T           (M=8192, N=512, K=512)
    mma_gemm_big<false,false><<<dim3(Hh/128, (Bb*Ss)/128), 256>>>(
        enc, Hh, attn_W + Hh, 2*Hh, We, Hh, nullptr, Bb*Ss, Hh, Hh);

    // 4) scores, softmax+context
    score_kernel<<<dim3(Bb, Ss/8), 256>>>(v);
    ctx_kernel<<<dim3(Bb, Hh/128), 128>>>(enc);

    // 5) gates = rnn_in @ W_ih^T              (M=128, N=2048, K=1024)
    mma_gemm_big<false,false><<<dim3((4*Hh)/128, 1), 256>>>(
        rnn_in, 2*Hh, W_ih, 2*Hh, gates, 4*Hh, nullptr, Bb, 4*Hh, 2*Hh);

    // 6) gates += h0 @ W_hh^T                 (M=128, N=2048, K=512)
    mma_gemm_big<true,false><<<dim3((4*Hh)/128, 1), 256>>>(
        h0, Hh, W_hh, Hh, gates, 4*Hh, nullptr, Bb, 4*Hh, Hh);

    // 7) LSTM pointwise -> h_new, c_new
    lstm_kernel<<<Bb, Hh>>>(c0, b_ih, b_hh, out);

    // 8) prediction = h_new @ fc_W^T + fc_b   (M=128, N=32000, K=512)
    const float* h_new = out + (size_t)Bb * Vv;
    mma_gemm_big<false,true><<<dim3(Vv/128, 1), 256>>>(
        h_new, Hh, fc_W, Hh, out, Vv, fc_b, Bb, Vv, Hh);
}

// round 6
// speedup vs baseline: 3.8662x; 1.7958x over previous
#include <cuda_runtime.h>
#include <math.h>
#include <stdint.h>

#define Vv 32000
#define Hh 512
#define Bb 128
#define Ss 64

#define WH_SPLIT 4
#define G_SPLIT  8

// ---- scratch (single __device__ global, no allocations) ----
// P_wh[4][B*H] | We[B*S*H] | rnn3[B*3H] | P_g[8][B*4H] | scores[B*S]
#define OFF_WH   0
#define OFF_WE   (WH_SPLIT*Bb*Hh)                       // 262144
#define OFF_RNN  (OFF_WE + Bb*Ss*Hh)                    // 4456448
#define OFF_GATE (OFF_RNN + Bb*3*Hh)                    // 4653056
#define OFF_SC   (OFF_GATE + G_SPLIT*Bb*4*Hh)           // 6750208
#define SCRATCH_TOTAL (OFF_SC + Bb*Ss)
__device__ float g_scratch[SCRATCH_TOTAL];

__device__ __forceinline__ float sigmoidf_(float x) {
    return 1.0f / (1.0f + __expf(-x));
}
__device__ __forceinline__ float tanh_fast(float x) {
    float y; asm("tanh.approx.f32 %0, %1;" : "=f"(y) : "f"(x)); return y;
}
__device__ __forceinline__ uint32_t f2tf32(float x) {
    uint32_t r; asm("cvt.rna.tf32.f32 %0, %1;" : "=r"(r) : "f"(x)); return r;
}
__device__ __forceinline__ void mma_tf32(float c[4],
    uint32_t a0, uint32_t a1, uint32_t a2, uint32_t a3,
    uint32_t b0, uint32_t b1)
{
    asm volatile(
        "mma.sync.aligned.m16n8k8.row.col.f32.tf32.tf32.f32 "
        "{%0,%1,%2,%3}, {%4,%5,%6,%7}, {%8,%9}, {%0,%1,%2,%3};"
        : "+f"(c[0]), "+f"(c[1]), "+f"(c[2]), "+f"(c[3])
        : "r"(a0), "r"(a1), "r"(a2), "r"(a3), "r"(b0), "r"(b1));
}
__device__ __forceinline__ void ldsm_x4(uint32_t& r0, uint32_t& r1,
                                        uint32_t& r2, uint32_t& r3,
                                        uint32_t saddr)
{
    asm volatile("ldmatrix.sync.aligned.m8n8.x4.shared.b16 {%0,%1,%2,%3}, [%4];"
                 : "=r"(r0), "=r"(r1), "=r"(r2), "=r"(r3) : "r"(saddr));
}

// ============================================================
// tf32 GEMM v3: C[M,N](+slice) = A[M,K] @ Bcat[N,K]^T (+bias)
// Bcat: B0 (k < Kswitch, ldb0) then B1 (k >= Kswitch, ldb1).
// BM=128, BN=128, BK=32; tf32 stored in smem (CVT at store);
// register double-buffered global loads; ldmatrix fragments.
// grid = (N/128, M/128, nsplit); slice z handles K range
// [z*Kslice, (z+1)*Kslice), writes C + z*cslice.
// Requires M%128==0, N%128==0, Kslice%32==0, rows 16B-aligned.
// ============================================================
#define SST 36   // smem row stride (words): conflict-free LDSM + STS.128
#define ABUF_W (128*SST)

template<bool BIAS>
__global__ __launch_bounds__(256)
void mma3(const float* __restrict__ A, int lda,
          const float* __restrict__ B0, int ldb0,
          const float* __restrict__ B1, int ldb1, int Kswitch,
          float* __restrict__ C, int ldc, int cslice,
          const float* __restrict__ bias, int Kslice)
{
    extern __shared__ uint32_t sh[];   // As[2][128][SST] | Bs[2][128][SST]

    const int m0 = blockIdx.y * 128;
    const int n0 = blockIdx.x * 128;
    const int kbase = blockIdx.z * Kslice;
    C += (size_t)blockIdx.z * cslice;

    const int t    = threadIdx.x;
    const int lane = t & 31;
    const int warp = t >> 5;
    const int wm = warp & 1;
    const int wn = warp >> 1;
    const int g  = lane >> 2;
    const int tg = lane & 3;

    const uint32_t as_base = (uint32_t)__cvta_generic_to_shared(sh);
    const uint32_t bs_base = as_base + 2u * ABUF_W * 4u;
    const uint32_t a_loff = (uint32_t)(((lane & 15) * SST + ((lane >> 4) << 2)) * 4);
    const uint32_t b_loff = (uint32_t)((((lane & 7) + ((lane >> 4) << 3)) * SST
                                        + (((lane >> 3) & 1) << 2)) * 4);

    // per-thread load map: 4 chunks; row = idx>>3, col4 = (idx&7)*4
    const int lrow = t >> 3;          // base row for chunk 0 (stride 32 rows/chunk)
    const int lcol = (t & 7) * 4;

    float4 abuf[4], bbuf[4];

    auto ldg_stage = [&](int kc) {
        #pragma unroll
        for (int i = 0; i < 4; i++) {
            int r = lrow + 32 * i;
            int kabs = kbase + kc + lcol;
            abuf[i] = *(const float4*)&A[(size_t)(m0 + r) * lda + kabs];
            const float* bp = (kabs < Kswitch)
                ? (B0 + (size_t)(n0 + r) * ldb0 + kabs)
                : (B1 + (size_t)(n0 + r) * ldb1 + (kabs - Kswitch));
            bbuf[i] = *(const float4*)bp;
        }
    };
    auto sts_stage = [&](int s) {
        uint32_t* As = sh + (size_t)s * ABUF_W;
        uint32_t* Bs = sh + 2 * ABUF_W + (size_t)s * ABUF_W;
        #pragma unroll
        for (int i = 0; i < 4; i++) {
            int r = lrow + 32 * i;
            uint4 ua = make_uint4(f2tf32(abuf[i].x), f2tf32(abuf[i].y),
                                  f2tf32(abuf[i].z), f2tf32(abuf[i].w));
            *(uint4*)&As[r * SST + lcol] = ua;
            uint4 ub = make_uint4(f2tf32(bbuf[i].x), f2tf32(bbuf[i].y),
                                  f2tf32(bbuf[i].z), f2tf32(bbuf[i].w));
            *(uint4*)&Bs[r * SST + lcol] = ub;
        }
    };

    float acc[4][4][4];
    #pragma unroll
    for (int mi = 0; mi < 4; mi++)
        #pragma unroll
        for (int ni = 0; ni < 4; ni++)
            #pragma unroll
            for (int k = 0; k < 4; k++) acc[mi][ni][k] = 0.0f;

    const int nk = Kslice >> 5;

    ldg_stage(0);
    sts_stage(0);
    if (nk > 1) ldg_stage(32);
    __syncthreads();

    for (int kt = 0; kt < nk; kt++) {
        const int cur = kt & 1;
        const uint32_t abufp = as_base + (uint32_t)cur * (ABUF_W * 4u);
        const uint32_t bbufp = bs_base + (uint32_t)cur * (ABUF_W * 4u);

        #pragma unroll
        for (int kk = 0; kk < 32; kk += 8) {
            uint32_t af[4][4], bf[4][2];
            #pragma unroll
            for (int mi = 0; mi < 4; mi++) {
                uint32_t addr = abufp + (uint32_t)(((wm * 64 + mi * 16) * SST + kk) * 4) + a_loff;
                ldsm_x4(af[mi][0], af[mi][1], af[mi][2], af[mi][3], addr);
            }
            {
                uint32_t addr0 = bbufp + (uint32_t)(((wn * 32) * SST + kk) * 4) + b_loff;
                uint32_t addr1 = bbufp + (uint32_t)(((wn * 32 + 16) * SST + kk) * 4) + b_loff;
                ldsm_x4(bf[0][0], bf[0][1], bf[1][0], bf[1][1], addr0);
                ldsm_x4(bf[2][0], bf[2][1], bf[3][0], bf[3][1], addr1);
            }
            #pragma unroll
            for (int mi = 0; mi < 4; mi++)
                #pragma unroll
                for (int ni = 0; ni < 4; ni++)
                    mma_tf32(acc[mi][ni],
                             af[mi][0], af[mi][1], af[mi][2], af[mi][3],
                             bf[ni][0], bf[ni][1]);
        }

        if (kt + 1 < nk) {
            sts_stage(cur ^ 1);           // regs for kt+1 -> other buffer
            __syncthreads();
            if (kt + 2 < nk) ldg_stage((kt + 2) << 5);
        }
    }

    #pragma unroll
    for (int mi = 0; mi < 4; mi++) {
        #pragma unroll
        for (int ci = 0; ci < 2; ci++) {
            int m = m0 + wm * 64 + mi * 16 + g + ci * 8;
            #pragma unroll
            for (int ni = 0; ni < 4; ni++) {
                int n = n0 + wn * 32 + ni * 8 + tg * 2;
                float2 vo;
                vo.x = acc[mi][ni][ci * 2 + 0];
                vo.y = acc[mi][ni][ci * 2 + 1];
                if (BIAS) { vo.x += bias[n]; vo.y += bias[n + 1]; }
                *(float2*)&C[(size_t)m * ldc + n] = vo;
            }
        }
    }
}
#define MMA3_SMEM (4 * ABUF_W * 4)   // 73728 bytes

// ============================================================
// Embedding gather + h0 copy -> rnn3 = [embedded | context | h0]
// ============================================================
__global__ void embed_kernel(const int* __restrict__ input_ids,
                             const float* __restrict__ emb,
                             const float* __restrict__ h0)
{
    int b = blockIdx.x;
    int h = threadIdx.x;          // 512
    float* rnn3 = g_scratch + OFF_RNN;
    int idx = input_ids[b];
    rnn3[(size_t)b * (3*Hh) + h]          = emb[(size_t)idx * Hh + h];
    rnn3[(size_t)b * (3*Hh) + 2*Hh + h]   = h0[(size_t)b * Hh + h];
}

// ============================================================
// scores[b][s] = v . tanh(sum_z P_wh[z][b] + attn_b + We[b,s])
// ============================================================
__global__ __launch_bounds__(256)
void score_kernel(const float* __restrict__ attn_b,
                  const float* __restrict__ v)
{
    const int b = blockIdx.x;
    const int s = blockIdx.y * 8 + (threadIdx.x >> 5);
    const int lane = threadIdx.x & 31;

    const float4* p0 = (const float4*)(g_scratch + OFF_WH + 0*Bb*Hh + (size_t)b * Hh);
    const float4* p1 = (const float4*)(g_scratch + OFF_WH + 1*Bb*Hh + (size_t)b * Hh);
    const float4* p2 = (const float4*)(g_scratch + OFF_WH + 2*Bb*Hh + (size_t)b * Hh);
    const float4* p3 = (const float4*)(g_scratch + OFF_WH + 3*Bb*Hh + (size_t)b * Hh);
    const float4* We4 = (const float4*)(g_scratch + OFF_WE + ((size_t)b * Ss + s) * Hh);
    const float4* ab4 = (const float4*)attn_b;
    const float4* v4  = (const float4*)v;

    float sum = 0.0f;
    #pragma unroll
    for (int i = lane; i < Hh/4; i += 32) {
        float4 a0 = p0[i], a1 = p1[i], a2 = p2[i], a3 = p3[i];
        float4 ab = ab4[i];
        float4 e = We4[i];
        float4 vv = v4[i];
        float wx = a0.x + a1.x + a2.x + a3.x + ab.x;
        float wy = a0.y + a1.y + a2.y + a3.y + ab.y;
        float wz = a0.z + a1.z + a2.z + a3.z + ab.z;
        float ww = a0.w + a1.w + a2.w + a3.w + ab.w;
        sum += vv.x * tanh_fast(wx + e.x);
        sum += vv.y * tanh_fast(wy + e.y);
        sum += vv.z * tanh_fast(wz + e.z);
        sum += vv.w * tanh_fast(ww + e.w);
    }

    #pragma unroll
    for (int off = 16; off > 0; off >>= 1)
        sum += __shfl_xor_sync(0xFFFFFFFFu, sum, off);
    if (lane == 0)
        g_scratch[OFF_SC + (size_t)b * Ss + s] = sum;
}

// ============================================================
// softmax over s + context -> rnn3[:, H:2H]
// ============================================================
__global__ __launch_bounds__(128)
void ctx_kernel(const float* __restrict__ enc)
{
    const int b = blockIdx.x;
    const int t = threadIdx.x;
    __shared__ float swgt[Ss];

    if (t < 32) {
        float x0 = g_scratch[OFF_SC + (size_t)b * Ss + t];
        float x1 = g_scratch[OFF_SC + (size_t)b * Ss + t + 32];
        float mx = fmaxf(x0, x1);
        #pragma unroll
        for (int off = 16; off > 0; off >>= 1)
            mx = fmaxf(mx, __shfl_xor_sync(0xFFFFFFFFu, mx, off));
        float e0 = expf(x0 - mx), e1 = expf(x1 - mx);
        float sum = e0 + e1;
        #pragma unroll
        for (int off = 16; off > 0; off >>= 1)
            sum += __shfl_xor_sync(0xFFFFFFFFu, sum, off);
        float inv = 1.0f / sum;
        swgt[t]      = e0 * inv;
        swgt[t + 32] = e1 * inv;
    }
    __syncthreads();

    int h = blockIdx.y * 128 + t;
    const float* encb = enc + (size_t)b * Ss * Hh + h;
    float a = 0.0f;
    #pragma unroll 16
    for (int s = 0; s < Ss; s++)
        a = fmaf(swgt[s], encb[(size_t)s * Hh], a);
    g_scratch[OFF_RNN + (size_t)b * 3 * Hh + Hh + h] = a;
}

// ============================================================
// LSTM pointwise: sum G_SPLIT gate partials + biases -> c_new, h_new
// ============================================================
__global__ void lstm_kernel(const float* __restrict__ c0,
                            const float* __restrict__ b_ih,
                            const float* __restrict__ b_hh,
                            float* __restrict__ out)
{
    int b = blockIdx.x;
    int h = threadIdx.x;
    const float* gp = g_scratch + OFF_GATE + (size_t)b * (4*Hh);

    float ig = b_ih[h]        + b_hh[h];
    float fg = b_ih[Hh + h]   + b_hh[Hh + h];
    float gg = b_ih[2*Hh + h] + b_hh[2*Hh + h];
    float og = b_ih[3*Hh + h] + b_hh[3*Hh + h];
    #pragma unroll
    for (int z = 0; z < G_SPLIT; z++) {
        const float* pz = gp + (size_t)z * (Bb * 4 * Hh);
        ig += pz[h];
        fg += pz[Hh + h];
        gg += pz[2*Hh + h];
        og += pz[3*Hh + h];
    }

    float cn = sigmoidf_(fg) * c0[(size_t)b * Hh + h]
             + sigmoidf_(ig) * tanhf(gg);
    float hn = sigmoidf_(og) * tanhf(cn);

    out[(size_t)Bb * Vv + (size_t)b * Hh + h] = hn;
    out[(size_t)Bb * Vv + (size_t)Bb * Hh + (size_t)b * Hh + h] = cn;
}

// ============================================================
// kernel_launch
// ============================================================
extern "C" void kernel_launch(void* const* d_in, const int* in_sizes, int n_in,
                              void* d_out, int out_size)
{
    const int*   input_ids = (const int*)  d_in[0];
    const float* h0        = (const float*)d_in[1];
    const float* c0        = (const float*)d_in[2];
    const float* enc       = (const float*)d_in[3];
    const float* emb       = (const float*)d_in[4];
    const float* attn_W    = (const float*)d_in[5];
    const float* attn_b    = (const float*)d_in[6];
    const float* v         = (const float*)d_in[7];
    const float* W_ih      = (const float*)d_in[8];
    const float* W_hh      = (const float*)d_in[9];
    const float* b_ih      = (const float*)d_in[10];
    const float* b_hh      = (const float*)d_in[11];
    const float* fc_W      = (const float*)d_in[12];
    const float* fc_b      = (const float*)d_in[13];
    float* out = (float*)d_out;

    float* scratch = nullptr;
    cudaGetSymbolAddress((void**)&scratch, g_scratch);
    float* P_wh  = scratch + OFF_WH;
    float* We    = scratch + OFF_WE;
    float* rnn3  = scratch + OFF_RNN;
    float* P_g   = scratch + OFF_GATE;

    cudaFuncSetAttribute(mma3<false>, cudaFuncAttributeMaxDynamicSharedMemorySize, MMA3_SMEM);
    cudaFuncSetAttribute(mma3<true>,  cudaFuncAttributeMaxDynamicSharedMemorySize, MMA3_SMEM);

    const int BIG = 1 << 30;

    // 1) embedded + h0 copy -> rnn3
    embed_kernel<<<Bb, Hh>>>(input_ids, emb, h0);

    // 2) P_wh[z] = h0 @ attn_W[:, :H]^T  (split-K 4; M=128, N=512, K=512)
    mma3<false><<<dim3(Hh/128, 1, WH_SPLIT), 256, MMA3_SMEM>>>(
        h0, Hh, attn_W, 2*Hh, attn_W, 2*Hh, BIG,
        P_wh, Hh, Bb*Hh, nullptr, Hh/WH_SPLIT);

    // 3) We = enc @ attn_W[:, H:]^T      (M=8192, N=512, K=512)
    mma3<false><<<dim3(Hh/128, (Bb*Ss)/128, 1), 256, MMA3_SMEM>>>(
        enc, Hh, attn_W + Hh, 2*Hh, attn_W + Hh, 2*Hh, BIG,
        We, Hh, 0, nullptr, Hh);

    // 4) scores (partial-sum of Wh inside), softmax + context
    score_kernel<<<dim3(Bb, Ss/8), 256>>>(attn_b, v);
    ctx_kernel<<<dim3(Bb, Hh/128), 128>>>(enc);

    // 5) P_g[z] = rnn3 @ [W_ih | W_hh]^T (split-K 8; M=128, N=2048, K=1536)
    mma3<false><<<dim3((4*Hh)/128, 1, G_SPLIT), 256, MMA3_SMEM>>>(
        rnn3, 3*Hh, W_ih, 2*Hh, W_hh, Hh, 2*Hh,
        P_g, 4*Hh, Bb*4*Hh, nullptr, (3*Hh)/G_SPLIT);

    // 6) LSTM pointwise (sums partials) -> h_new, c_new
    lstm_kernel<<<Bb, Hh>>>(c0, b_ih, b_hh, out);

    // 7) prediction = h_new @ fc_W^T + fc_b  (M=128, N=32000, K=512)
    const float* h_new = out + (size_t)Bb * Vv;
    mma3<true><<<dim3(Vv/128, 1, 1), 256, MMA3_SMEM>>>(
        h_new, Hh, fc_W, Hh, fc_W, Hh, BIG,
        out, Vv, 0, fc_b, Hh);
}

// round 7
// speedup vs baseline: 4.7526x; 1.2293x over previous
#include <cuda_runtime.h>
#include <cuda_fp16.h>
#include <math.h>
#include <stdint.h>

#define Vv 32000
#define Hh 512
#define Bb 128
#define Ss 64

#define WH_SPLIT 4
#define G_SPLIT  8

// ---- scratch ----
// P_wh[4][B*H] | We[B*S*H] | rnn3[B*3H] | P_g[8][B*4H] | scores[B*S]
#define OFF_WH   0
#define OFF_WE   (WH_SPLIT*Bb*Hh)
#define OFF_RNN  (OFF_WE + Bb*Ss*Hh)
#define OFF_GATE (OFF_RNN + Bb*3*Hh)
#define OFF_SC   (OFF_GATE + G_SPLIT*Bb*4*Hh)
#define SCRATCH_TOTAL (OFF_SC + Bb*Ss)
__device__ float g_scratch[SCRATCH_TOTAL];

__device__ __forceinline__ float sigmoidf_(float x) {
    return 1.0f / (1.0f + __expf(-x));
}
__device__ __forceinline__ float tanh_fast(float x) {
    float y; asm("tanh.approx.f32 %0, %1;" : "=f"(y) : "f"(x)); return y;
}
__device__ __forceinline__ uint32_t pack_h2(float lo, float hi) {
    uint32_t r;
    asm("cvt.rn.f16x2.f32 %0, %1, %2;" : "=r"(r) : "f"(hi), "f"(lo));
    return r;
}
__device__ __forceinline__ void mma_f16(float c[4],
    uint32_t a0, uint32_t a1, uint32_t a2, uint32_t a3,
    uint32_t b0, uint32_t b1)
{
    asm volatile(
        "mma.sync.aligned.m16n8k16.row.col.f32.f16.f16.f32 "
        "{%0,%1,%2,%3}, {%4,%5,%6,%7}, {%8,%9}, {%0,%1,%2,%3};"
        : "+f"(c[0]), "+f"(c[1]), "+f"(c[2]), "+f"(c[3])
        : "r"(a0), "r"(a1), "r"(a2), "r"(a3), "r"(b0), "r"(b1));
}
__device__ __forceinline__ void ldsm_x4(uint32_t& r0, uint32_t& r1,
                                        uint32_t& r2, uint32_t& r3,
                                        uint32_t saddr)
{
    asm volatile("ldmatrix.sync.aligned.m8n8.x4.shared.b16 {%0,%1,%2,%3}, [%4];"
                 : "=r"(r0), "=r"(r1), "=r"(r2), "=r"(r3) : "r"(saddr));
}

// ============================================================
// fp16 GEMM: C[M,N](+slice) = A[M,K] @ Bcat[N,K]^T (+bias)
// Bcat: B0 (k < Kswitch, ldb0) then B1 (k >= Kswitch, ldb1).
// BM=128, BN=128, BK=32; fp32->fp16 CVT at smem store; reg
// double-buffered LDG; ldmatrix frags; mma m16n8k16.
// grid = (N/128, M/128, nsplit); slice z: K range [z*Kslice, ...),
// writes C + z*cslice.  M%128==0, N%128==0, Kslice%32==0.
// ============================================================
#define SSTH 40                       // halves per smem row (80B): conflict-free LDSM
#define HBUF (128*SSTH)               // halves per stage buffer
#define MMA3H_SMEM (4*HBUF*2)         // 40960 bytes

template<bool BIAS>
__global__ __launch_bounds__(256)
void mma3h(const float* __restrict__ A, int lda,
           const float* __restrict__ B0, int ldb0,
           const float* __restrict__ B1, int ldb1, int Kswitch,
           float* __restrict__ C, int ldc, int cslice,
           const float* __restrict__ bias, int Kslice)
{
    extern __shared__ __half shh[];   // As[2][128][SSTH] | Bs[2][128][SSTH]

    const int m0 = blockIdx.y * 128;
    const int n0 = blockIdx.x * 128;
    const int kbase = blockIdx.z * Kslice;
    C += (size_t)blockIdx.z * cslice;

    const int t    = threadIdx.x;
    const int lane = t & 31;
    const int warp = t >> 5;
    const int wm = warp & 1;
    const int wn = warp >> 1;
    const int g  = lane >> 2;
    const int tg = lane & 3;

    const uint32_t as_base = (uint32_t)__cvta_generic_to_shared(shh);
    const uint32_t bs_base = as_base + 2u * HBUF * 2u;
    // A ldsm lane offset: lanes 0-15 -> rows m+(lane&15) @k, 16-31 -> same rows @k+8
    const uint32_t a_loff = (uint32_t)(((lane & 15) * SSTH + ((lane >> 4) << 3)) * 2);
    // B ldsm lane offset: 8-row groups, k/k+8 select
    const uint32_t b_loff = (uint32_t)((((lane & 7) + ((lane >> 4) << 3)) * SSTH
                                        + (((lane >> 3) & 1) << 3)) * 2);

    const int lrow = t >> 3;          // 0..31 (4 chunks of 32 rows)
    const int lcol = (t & 7) * 4;     // float index within K-tile

    float4 abuf[4], bbuf[4];

    auto ldg_stage = [&](int kc) {
        #pragma unroll
        for (int i = 0; i < 4; i++) {
            int r = lrow + 32 * i;
            int kabs = kbase + kc + lcol;
            abuf[i] = *(const float4*)&A[(size_t)(m0 + r) * lda + kabs];
            const float* bp = (kabs < Kswitch)
                ? (B0 + (size_t)(n0 + r) * ldb0 + kabs)
                : (B1 + (size_t)(n0 + r) * ldb1 + (kabs - Kswitch));
            bbuf[i] = *(const float4*)bp;
        }
    };
    auto sts_stage = [&](int s) {
        __half* As = shh + (size_t)s * HBUF;
        __half* Bs = shh + 2 * HBUF + (size_t)s * HBUF;
        #pragma unroll
        for (int i = 0; i < 4; i++) {
            int r = lrow + 32 * i;
            uint2 ua = make_uint2(pack_h2(abuf[i].x, abuf[i].y),
                                  pack_h2(abuf[i].z, abuf[i].w));
            *(uint2*)&As[r * SSTH + lcol] = ua;
            uint2 ub = make_uint2(pack_h2(bbuf[i].x, bbuf[i].y),
                                  pack_h2(bbuf[i].z, bbuf[i].w));
            *(uint2*)&Bs[r * SSTH + lcol] = ub;
        }
    };

    float acc[4][4][4];
    #pragma unroll
    for (int mi = 0; mi < 4; mi++)
        #pragma unroll
        for (int ni = 0; ni < 4; ni++)
            #pragma unroll
            for (int k = 0; k < 4; k++) acc[mi][ni][k] = 0.0f;

    const int nk = Kslice >> 5;

    ldg_stage(0);
    sts_stage(0);
    if (nk > 1) ldg_stage(32);
    __syncthreads();

    for (int kt = 0; kt < nk; kt++) {
        const int cur = kt & 1;
        const uint32_t abufp = as_base + (uint32_t)cur * (HBUF * 2u);
        const uint32_t bbufp = bs_base + (uint32_t)cur * (HBUF * 2u);

        #pragma unroll
        for (int kk = 0; kk < 32; kk += 16) {
            uint32_t af[4][4], bf[4][2];
            #pragma unroll
            for (int mi = 0; mi < 4; mi++) {
                uint32_t addr = abufp
                    + (uint32_t)(((wm * 64 + mi * 16) * SSTH + kk) * 2) + a_loff;
                ldsm_x4(af[mi][0], af[mi][1], af[mi][2], af[mi][3], addr);
            }
            #pragma unroll
            for (int p = 0; p < 2; p++) {
                uint32_t addr = bbufp
                    + (uint32_t)(((wn * 32 + p * 16) * SSTH + kk) * 2) + b_loff;
                ldsm_x4(bf[2*p][0], bf[2*p][1], bf[2*p+1][0], bf[2*p+1][1], addr);
            }
            #pragma unroll
            for (int mi = 0; mi < 4; mi++)
                #pragma unroll
                for (int ni = 0; ni < 4; ni++)
                    mma_f16(acc[mi][ni],
                            af[mi][0], af[mi][1], af[mi][2], af[mi][3],
                            bf[ni][0], bf[ni][1]);
        }

        if (kt + 1 < nk) {
            sts_stage(cur ^ 1);
            __syncthreads();
            if (kt + 2 < nk) ldg_stage((kt + 2) << 5);
        }
    }

    #pragma unroll
    for (int mi = 0; mi < 4; mi++) {
        #pragma unroll
        for (int ci = 0; ci < 2; ci++) {
            int m = m0 + wm * 64 + mi * 16 + g + ci * 8;
            #pragma unroll
            for (int ni = 0; ni < 4; ni++) {
                int n = n0 + wn * 32 + ni * 8 + tg * 2;
                float2 vo;
                vo.x = acc[mi][ni][ci * 2 + 0];
                vo.y = acc[mi][ni][ci * 2 + 1];
                if (BIAS) { vo.x += bias[n]; vo.y += bias[n + 1]; }
                *(float2*)&C[(size_t)m * ldc + n] = vo;
            }
        }
    }
}

// ============================================================
// Embedding gather + h0 copy -> rnn3 = [embedded | context | h0]
// ============================================================
__global__ void embed_kernel(const int* __restrict__ input_ids,
                             const float* __restrict__ emb,
                             const float* __restrict__ h0)
{
    int b = blockIdx.x;
    int h = threadIdx.x;          // 512
    float* rnn3 = g_scratch + OFF_RNN;
    int idx = input_ids[b];
    rnn3[(size_t)b * (3*Hh) + h]        = emb[(size_t)idx * Hh + h];
    rnn3[(size_t)b * (3*Hh) + 2*Hh + h] = h0[(size_t)b * Hh + h];
}

// ============================================================
// Wh reduce: P_wh[0] = sum_z P_wh[z] + attn_b   (in-place, float4)
// grid 128 x 128 threads: one float4 per thread
// ============================================================
__global__ void whsum_kernel(const float* __restrict__ attn_b)
{
    int i = blockIdx.x * 128 + threadIdx.x;     // 0 .. B*H/4-1
    int hc = i & (Hh/4 - 1);
    float4* p0 = (float4*)(g_scratch + OFF_WH);
    const float4* p1 = (const float4*)(g_scratch + OFF_WH + 1*Bb*Hh);
    const float4* p2 = (const float4*)(g_scratch + OFF_WH + 2*Bb*Hh);
    const float4* p3 = (const float4*)(g_scratch + OFF_WH + 3*Bb*Hh);
    float4 a = p0[i], b = p1[i], c = p2[i], d = p3[i];
    float4 ab = ((const float4*)attn_b)[hc];
    a.x += b.x + c.x + d.x + ab.x;
    a.y += b.y + c.y + d.y + ab.y;
    a.z += b.z + c.z + d.z + ab.z;
    a.w += b.w + c.w + d.w + ab.w;
    p0[i] = a;
}

// ============================================================
// scores[b][s] = v . tanh(Wh'[b] + We[b,s])
// ============================================================
__global__ __launch_bounds__(256)
void score_kernel(const float* __restrict__ v)
{
    const int b = blockIdx.x;
    const int s = blockIdx.y * 8 + (threadIdx.x >> 5);
    const int lane = threadIdx.x & 31;

    const float4* Wh4 = (const float4*)(g_scratch + OFF_WH + (size_t)b * Hh);
    const float4* We4 = (const float4*)(g_scratch + OFF_WE + ((size_t)b * Ss + s) * Hh);
    const float4* v4  = (const float4*)v;

    float sum = 0.0f;
    #pragma unroll
    for (int i = lane; i < Hh/4; i += 32) {
        float4 w = Wh4[i];
        float4 e = We4[i];
        float4 vv = v4[i];
        sum += vv.x * tanh_fast(w.x + e.x);
        sum += vv.y * tanh_fast(w.y + e.y);
        sum += vv.z * tanh_fast(w.z + e.z);
        sum += vv.w * tanh_fast(w.w + e.w);
    }

    #pragma unroll
    for (int off = 16; off > 0; off >>= 1)
        sum += __shfl_xor_sync(0xFFFFFFFFu, sum, off);
    if (lane == 0)
        g_scratch[OFF_SC + (size_t)b * Ss + s] = sum;
}

// ============================================================
// softmax over s + context -> rnn3[:, H:2H]
// ============================================================
__global__ __launch_bounds__(128)
void ctx_kernel(const float* __restrict__ enc)
{
    const int b = blockIdx.x;
    const int t = threadIdx.x;
    __shared__ float swgt[Ss];

    if (t < 32) {
        float x0 = g_scratch[OFF_SC + (size_t)b * Ss + t];
        float x1 = g_scratch[OFF_SC + (size_t)b * Ss + t + 32];
        float mx = fmaxf(x0, x1);
        #pragma unroll
        for (int off = 16; off > 0; off >>= 1)
            mx = fmaxf(mx, __shfl_xor_sync(0xFFFFFFFFu, mx, off));
        float e0 = expf(x0 - mx), e1 = expf(x1 - mx);
        float sum = e0 + e1;
        #pragma unroll
        for (int off = 16; off > 0; off >>= 1)
            sum += __shfl_xor_sync(0xFFFFFFFFu, sum, off);
        float inv = 1.0f / sum;
        swgt[t]      = e0 * inv;
        swgt[t + 32] = e1 * inv;
    }
    __syncthreads();

    int h = blockIdx.y * 128 + t;
    const float* encb = enc + (size_t)b * Ss * Hh + h;
    float a = 0.0f;
    #pragma unroll 16
    for (int s = 0; s < Ss; s++)
        a = fmaf(swgt[s], encb[(size_t)s * Hh], a);
    g_scratch[OFF_RNN + (size_t)b * 3 * Hh + Hh + h] = a;
}

// ============================================================
// LSTM pointwise: sum G_SPLIT gate partials + biases
// ============================================================
__global__ void lstm_kernel(const float* __restrict__ c0,
                            const float* __restrict__ b_ih,
                            const float* __restrict__ b_hh,
                            float* __restrict__ out)
{
    int b = blockIdx.x;
    int h = threadIdx.x;
    const float* gp = g_scratch + OFF_GATE + (size_t)b * (4*Hh);

    float ig = b_ih[h]        + b_hh[h];
    float fg = b_ih[Hh + h]   + b_hh[Hh + h];
    float gg = b_ih[2*Hh + h] + b_hh[2*Hh + h];
    float og = b_ih[3*Hh + h] + b_hh[3*Hh + h];
    #pragma unroll
    for (int z = 0; z < G_SPLIT; z++) {
        const float* pz = gp + (size_t)z * (Bb * 4 * Hh);
        ig += pz[h];
        fg += pz[Hh + h];
        gg += pz[2*Hh + h];
        og += pz[3*Hh + h];
    }

    float cn = sigmoidf_(fg) * c0[(size_t)b * Hh + h]
             + sigmoidf_(ig) * tanhf(gg);
    float hn = sigmoidf_(og) * tanhf(cn);

    out[(size_t)Bb * Vv + (size_t)b * Hh + h] = hn;
    out[(size_t)Bb * Vv + (size_t)Bb * Hh + (size_t)b * Hh + h] = cn;
}

// ============================================================
// kernel_launch
// ============================================================
extern "C" void kernel_launch(void* const* d_in, const int* in_sizes, int n_in,
                              void* d_out, int out_size)
{
    const int*   input_ids = (const int*)  d_in[0];
    const float* h0        = (const float*)d_in[1];
    const float* c0        = (const float*)d_in[2];
    const float* enc       = (const float*)d_in[3];
    const float* emb       = (const float*)d_in[4];
    const float* attn_W    = (const float*)d_in[5];
    const float* attn_b    = (const float*)d_in[6];
    const float* v         = (const float*)d_in[7];
    const float* W_ih      = (const float*)d_in[8];
    const float* W_hh      = (const float*)d_in[9];
    const float* b_ih      = (const float*)d_in[10];
    const float* b_hh      = (const float*)d_in[11];
    const float* fc_W      = (const float*)d_in[12];
    const float* fc_b      = (const float*)d_in[13];
    float* out = (float*)d_out;

    float* scratch = nullptr;
    cudaGetSymbolAddress((void**)&scratch, g_scratch);
    float* P_wh  = scratch + OFF_WH;
    float* We    = scratch + OFF_WE;
    float* rnn3  = scratch + OFF_RNN;
    float* P_g   = scratch + OFF_GATE;

    const int BIG = 1 << 30;

    // 1) embedded + h0 copy -> rnn3
    embed_kernel<<<Bb, Hh>>>(input_ids, emb, h0);

    // 2) P_wh[z] = h0 @ attn_W[:, :H]^T  (split-K 4)
    mma3h<false><<<dim3(Hh/128, 1, WH_SPLIT), 256, MMA3H_SMEM>>>(
        h0, Hh, attn_W, 2*Hh, attn_W, 2*Hh, BIG,
        P_wh, Hh, Bb*Hh, nullptr, Hh/WH_SPLIT);

    // 3) We = enc @ attn_W[:, H:]^T      (M=8192, N=512, K=512)
    mma3h<false><<<dim3(Hh/128, (Bb*Ss)/128, 1), 256, MMA3H_SMEM>>>(
        enc, Hh, attn_W + Hh, 2*Hh, attn_W + Hh, 2*Hh, BIG,
        We, Hh, 0, nullptr, Hh);

    // 4) reduce Wh partials (+attn_b), scores, softmax + context
    whsum_kernel<<<Bb, 128>>>(attn_b);
    score_kernel<<<dim3(Bb, Ss/8), 256>>>(v);
    ctx_kernel<<<dim3(Bb, Hh/128), 128>>>(enc);

    // 5) P_g[z] = rnn3 @ [W_ih | W_hh]^T (split-K 8; K=1536)
    mma3h<false><<<dim3((4*Hh)/128, 1, G_SPLIT), 256, MMA3H_SMEM>>>(
        rnn3, 3*Hh, W_ih, 2*Hh, W_hh, Hh, 2*Hh,
        P_g, 4*Hh, Bb*4*Hh, nullptr, (3*Hh)/G_SPLIT);

    // 6) LSTM pointwise -> h_new, c_new
    lstm_kernel<<<Bb, Hh>>>(c0, b_ih, b_hh, out);

    // 7) prediction = h_new @ fc_W^T + fc_b  (M=128, N=32000, K=512)
    const float* h_new = out + (size_t)Bb * Vv;
    mma3h<true><<<dim3(Vv/128, 1, 1), 256, MMA3H_SMEM>>>(
        h_new, Hh, fc_W, Hh, fc_W, Hh, BIG,
        out, Vv, 0, fc_b, Hh);
}